// round 1
// baseline (speedup 1.0000x reference)
#include <cuda_runtime.h>
#include <math.h>

#define Nn   65536
#define Ee   262144
#define E2   327680
#define Bb   2048
#define Hh   4
#define Dd   192
#define HIDD 768
#define NEG_SLOPE 0.2f

// ---------------- device scratch (no runtime allocation allowed) ----------
__device__ float g_h [(size_t)Nn * HIDD];   // current node features (201 MB)
__device__ float g_xw[(size_t)Nn * HIDD];   // projected features    (201 MB)
__device__ float g_as[Nn * Hh];             // alpha_src per node/head
__device__ float g_ad[Nn * Hh];             // alpha_dst per node/head
__device__ int   g_deg[Nn];
__device__ int   g_off[Nn + 1];
__device__ int   g_cur[Nn];
__device__ int   g_srcs[E2];                // CSR: src node per incoming edge, bucketed by dst
__device__ int   g_start[Bb];
__device__ int   g_end[Bb];
__device__ float g_hg[(size_t)Bb * HIDD];

// ---------------- fp32 tiled GEMM: C[M,768] = A[M,768] @ B[768,768] (+bias) ----
__global__ __launch_bounds__(256) void sgemm768(
    const float* __restrict__ A, const float* __restrict__ Bm,
    float* __restrict__ C, const float* __restrict__ bias)
{
    __shared__ float As[16][128];
    __shared__ float Bs[16][128];

    const int tid = threadIdx.x;
    const int ty  = tid >> 4;          // 0..15
    const int tx  = tid & 15;          // 0..15
    const int rowBase = blockIdx.y * 128;
    const int colBase = blockIdx.x * 128;

    const int aRow = tid >> 2;         // 0..63
    const int aCol = (tid & 3) << 2;   // 0,4,8,12
    const int bRow = tid >> 5;         // 0..7
    const int bCol = (tid & 31) << 2;  // 0..124

    float acc[8][8];
#pragma unroll
    for (int i = 0; i < 8; i++)
#pragma unroll
        for (int j = 0; j < 8; j++) acc[i][j] = 0.f;

    const float* Aptr = A + (size_t)(rowBase + aRow) * HIDD + aCol;
    const float* Bptr = Bm + (size_t)bRow * HIDD + colBase + bCol;

    for (int k0 = 0; k0 < HIDD; k0 += 16) {
        float4 a0 = *(const float4*)(Aptr + k0);
        float4 a1 = *(const float4*)(Aptr + (size_t)64 * HIDD + k0);
        float4 b0 = *(const float4*)(Bptr + (size_t)k0 * HIDD);
        float4 b1 = *(const float4*)(Bptr + (size_t)(k0 + 8) * HIDD);

        As[aCol + 0][aRow] = a0.x;  As[aCol + 1][aRow] = a0.y;
        As[aCol + 2][aRow] = a0.z;  As[aCol + 3][aRow] = a0.w;
        As[aCol + 0][aRow + 64] = a1.x;  As[aCol + 1][aRow + 64] = a1.y;
        As[aCol + 2][aRow + 64] = a1.z;  As[aCol + 3][aRow + 64] = a1.w;
        *(float4*)&Bs[bRow][bCol]     = b0;
        *(float4*)&Bs[bRow + 8][bCol] = b1;
        __syncthreads();

#pragma unroll
        for (int k = 0; k < 16; k++) {
            float ar[8], br[8];
#pragma unroll
            for (int i = 0; i < 8; i++) ar[i] = As[k][ty * 8 + i];
#pragma unroll
            for (int j = 0; j < 8; j++) br[j] = Bs[k][tx * 8 + j];
#pragma unroll
            for (int i = 0; i < 8; i++)
#pragma unroll
                for (int j = 0; j < 8; j++) acc[i][j] += ar[i] * br[j];
        }
        __syncthreads();
    }

#pragma unroll
    for (int i = 0; i < 8; i++) {
        int r = rowBase + ty * 8 + i;
        float* Crow = C + (size_t)r * HIDD + colBase + tx * 8;
#pragma unroll
        for (int j = 0; j < 8; j++) {
            float v = acc[i][j];
            if (bias) v += bias[colBase + tx * 8 + j];
            Crow[j] = v;
        }
    }
}

// ---------------- per-node per-head attention coefficients --------------------
__global__ __launch_bounds__(256) void alpha_kernel(
    const float* __restrict__ xw,
    const float* __restrict__ asrc, const float* __restrict__ adst)
{
    int gw   = (blockIdx.x * blockDim.x + threadIdx.x) >> 5;
    int lane = threadIdx.x & 31;
    if (gw >= Nn * Hh) return;
    int n = gw >> 2;   // / Hh
    int h = gw & 3;
    const float* row = xw + (size_t)n * HIDD + h * Dd;
    const float* a1  = asrc + h * Dd;
    const float* a2  = adst + h * Dd;
    float ss = 0.f, sd = 0.f;
#pragma unroll
    for (int k = 0; k < 6; k++) {
        float v = row[lane + 32 * k];
        ss += v * a1[lane + 32 * k];
        sd += v * a2[lane + 32 * k];
    }
#pragma unroll
    for (int o = 16; o > 0; o >>= 1) {
        ss += __shfl_xor_sync(0xffffffffu, ss, o);
        sd += __shfl_xor_sync(0xffffffffu, sd, o);
    }
    if (lane == 0) { g_as[gw] = ss; g_ad[gw] = sd; }
}

// ---------------- CSR build (edge topology; once per launch) ------------------
__global__ void count_kernel(const int* __restrict__ ei)
{
    int i = blockIdx.x * blockDim.x + threadIdx.x;
    if (i >= E2) return;
    int d = (i < Ee) ? ei[Ee + i] : (i - Ee);
    atomicAdd(&g_deg[d], 1);
}

__global__ __launch_bounds__(1024) void scan_kernel()
{
    __shared__ int s[1024];
    int t = threadIdx.x;
    int base = t * 64;
    int sum = 0;
    for (int i = 0; i < 64; i++) sum += g_deg[base + i];
    s[t] = sum;
    __syncthreads();
    for (int off = 1; off < 1024; off <<= 1) {
        int v   = s[t];
        int add = (t >= off) ? s[t - off] : 0;
        __syncthreads();
        s[t] = v + add;
        __syncthreads();
    }
    int excl = (t == 0) ? 0 : s[t - 1];
    for (int i = 0; i < 64; i++) {
        g_off[base + i] = excl;
        excl += g_deg[base + i];
    }
    if (t == 1023) g_off[Nn] = excl;
}

__global__ void scatter_kernel(const int* __restrict__ ei)
{
    int i = blockIdx.x * blockDim.x + threadIdx.x;
    if (i >= E2) return;
    int s, d;
    if (i < Ee) { s = ei[i]; d = ei[Ee + i]; }
    else        { s = i - Ee; d = s; }
    int p = atomicAdd(&g_cur[d], 1);
    g_srcs[g_off[d] + p] = s;
}

// ---------- fused: softmax-aggregate + bias + LayerNorm + ReLU + residual -----
// one block per dst node, one warp per head
__global__ __launch_bounds__(128) void agg_ln_kernel(
    const float* __restrict__ xw,
    const float* __restrict__ bias_l,
    const float* __restrict__ gamma_l,
    const float* __restrict__ beta_l,
    float* __restrict__ h)
{
    int i    = blockIdx.x;
    int w    = threadIdx.x >> 5;
    int lane = threadIdx.x & 31;
    float ad = g_ad[i * Hh + w];
    int s = g_off[i], e = g_off[i + 1];
    float acc[6] = {0.f, 0.f, 0.f, 0.f, 0.f, 0.f};
    float den = 0.f;
    int cb = w * Dd + lane;

    for (int p = s; p < e; p++) {
        int j = g_srcs[p];
        float t = g_as[j * Hh + w] + ad;
        t = (t > 0.f) ? t : NEG_SLOPE * t;
        float wt = expf(t);        // logits are O(0.1): max-subtraction unnecessary
        den += wt;
        const float* row = xw + (size_t)j * HIDD + cb;
#pragma unroll
        for (int k = 0; k < 6; k++) acc[k] += wt * row[32 * k];
    }

    float inv = 1.f / den;
    float lsum = 0.f, lsq = 0.f;
#pragma unroll
    for (int k = 0; k < 6; k++) {
        float v = acc[k] * inv + bias_l[cb + 32 * k];
        acc[k] = v;
        lsum += v;
        lsq  += v * v;
    }
#pragma unroll
    for (int o = 16; o > 0; o >>= 1) {
        lsum += __shfl_xor_sync(0xffffffffu, lsum, o);
        lsq  += __shfl_xor_sync(0xffffffffu, lsq,  o);
    }
    __shared__ float rs[4], rq[4];
    if (lane == 0) { rs[w] = lsum; rq[w] = lsq; }
    __syncthreads();
    float tot  = rs[0] + rs[1] + rs[2] + rs[3];
    float totq = rq[0] + rq[1] + rq[2] + rq[3];
    float mean = tot * (1.f / HIDD);
    float var  = totq * (1.f / HIDD) - mean * mean;
    float rstd = rsqrtf(var + 1e-5f);

#pragma unroll
    for (int k = 0; k < 6; k++) {
        int c = cb + 32 * k;
        float v = (acc[k] - mean) * rstd * gamma_l[c] + beta_l[c];
        v = fmaxf(v, 0.f);
        size_t idx = (size_t)i * HIDD + c;
        h[idx] = v + h[idx];       // ReLU + residual, in place (block owns node i)
    }
}

// ---------------- global mean pool (batch_vec is sorted -> contiguous ranges) --
__global__ void range_init()
{
    int b = blockIdx.x * blockDim.x + threadIdx.x;
    if (b < Bb) { g_start[b] = Nn; g_end[b] = 0; }
}

__global__ void range_kernel(const int* __restrict__ bv)
{
    int n = blockIdx.x * blockDim.x + threadIdx.x;
    if (n >= Nn) return;
    int b = bv[n];
    atomicMin(&g_start[b], n);
    atomicMax(&g_end[b], n + 1);
}

__global__ __launch_bounds__(256) void pool_kernel()
{
    int b = blockIdx.x;
    int s = g_start[b], e = g_end[b];
    float cnt = (e > s) ? (float)(e - s) : 1.0f;
    float invc = 1.f / cnt;
    for (int c = threadIdx.x; c < HIDD; c += 256) {
        float sum = 0.f;
        for (int n = s; n < e; n++) sum += g_h[(size_t)n * HIDD + c];
        g_hg[(size_t)b * HIDD + c] = sum * invc;
    }
}

// ------------------------------------------------------------------------------
extern "C" void kernel_launch(void* const* d_in, const int* in_sizes, int n_in,
                              void* d_out, int out_size)
{
    const float* x       = (const float*)d_in[0];
    const int*   ei      = (const int*)  d_in[1];
    const int*   bv      = (const int*)  d_in[2];
    const float* W       = (const float*)d_in[3];
    const float* att_src = (const float*)d_in[4];
    const float* att_dst = (const float*)d_in[5];
    const float* bias    = (const float*)d_in[6];
    const float* gamma   = (const float*)d_in[7];
    const float* beta    = (const float*)d_in[8];
    const float* out_w   = (const float*)d_in[9];
    const float* out_b   = (const float*)d_in[10];
    float* out = (float*)d_out;

    float *h_p, *xw_p, *hg_p;
    int *deg_p, *cur_p;
    cudaGetSymbolAddress((void**)&h_p,  g_h);
    cudaGetSymbolAddress((void**)&xw_p, g_xw);
    cudaGetSymbolAddress((void**)&hg_p, g_hg);
    cudaGetSymbolAddress((void**)&deg_p, g_deg);
    cudaGetSymbolAddress((void**)&cur_p, g_cur);

    cudaMemcpyAsync(h_p, x, (size_t)Nn * HIDD * sizeof(float),
                    cudaMemcpyDeviceToDevice);
    cudaMemsetAsync(deg_p, 0, Nn * sizeof(int));
    cudaMemsetAsync(cur_p, 0, Nn * sizeof(int));

    count_kernel  <<<(E2 + 255) / 256, 256>>>(ei);
    scan_kernel   <<<1, 1024>>>();
    scatter_kernel<<<(E2 + 255) / 256, 256>>>(ei);

    dim3 gemm_grid(HIDD / 128, Nn / 128);   // (6, 512)
    for (int l = 0; l < 2; l++) {
        sgemm768<<<gemm_grid, 256>>>(h_p, W + (size_t)l * HIDD * HIDD, xw_p, nullptr);
        alpha_kernel<<<(Nn * Hh) / 8, 256>>>(xw_p,
                                             att_src + l * Hh * Dd,
                                             att_dst + l * Hh * Dd);
        agg_ln_kernel<<<Nn, 128>>>(xw_p, bias + l * HIDD,
                                   gamma + l * HIDD, beta + l * HIDD, h_p);
    }

    range_init <<<Bb / 256, 256>>>();
    range_kernel<<<Nn / 256, 256>>>(bv);
    pool_kernel <<<Bb, 256>>>();

    sgemm768<<<dim3(HIDD / 128, Bb / 128), 256>>>(hg_p, out_w, out, out_b);
}

// round 4
// speedup vs baseline: 1.8947x; 1.8947x over previous
#include <cuda_runtime.h>
#include <cuda_bf16.h>
#include <math.h>
#include <stdint.h>

#define Nn   65536
#define Ee   262144
#define E2   327680
#define Bb   2048
#define Hh   4
#define Dd   192
#define HIDD 768
#define NEG_SLOPE 0.2f

// ---------------- device scratch ----------------
__device__ float g_h [(size_t)Nn * HIDD];
__device__ float g_xw[(size_t)Nn * HIDD];
__device__ float g_as[Nn * Hh];
__device__ float g_ad[Nn * Hh];
__device__ int   g_deg[Nn];
__device__ int   g_off[Nn + 1];
__device__ int   g_cur[Nn];
__device__ int   g_srcs[E2];
__device__ int   g_start[Bb];
__device__ int   g_end[Bb];
__device__ float g_hg[(size_t)Bb * HIDD];
__device__ __nv_bfloat16 g_ah[(size_t)Nn * HIDD];   // A hi
__device__ __nv_bfloat16 g_al[(size_t)Nn * HIDD];   // A lo
__device__ __nv_bfloat16 g_bh[HIDD * HIDD];         // B (=W^T) hi
__device__ __nv_bfloat16 g_bl[HIDD * HIDD];         // B lo

// ---------------- helpers ----------------
__device__ __forceinline__ uint32_t smem_u32(const void* p) {
    uint32_t a;
    asm("{ .reg .u64 t; cvta.to.shared.u64 t, %1; cvt.u32.u64 %0, t; }" : "=r"(a) : "l"(p));
    return a;
}

__device__ __forceinline__ void ldm_x4(uint32_t* r, uint32_t addr) {
    asm volatile("ldmatrix.sync.aligned.m8n8.x4.shared.b16 {%0,%1,%2,%3}, [%4];"
        : "=r"(r[0]), "=r"(r[1]), "=r"(r[2]), "=r"(r[3]) : "r"(addr));
}

__device__ __forceinline__ void mma_bf16(float* d, const uint32_t* a, uint32_t b0, uint32_t b1) {
    asm volatile("mma.sync.aligned.m16n8k16.row.col.f32.bf16.bf16.f32 "
        "{%0,%1,%2,%3}, {%4,%5,%6,%7}, {%8,%9}, {%0,%1,%2,%3};"
        : "+f"(d[0]), "+f"(d[1]), "+f"(d[2]), "+f"(d[3])
        : "r"(a[0]), "r"(a[1]), "r"(a[2]), "r"(a[3]), "r"(b0), "r"(b1));
}

#define CPA(dst, src) \
    asm volatile("cp.async.cg.shared.global [%0], [%1], 16;" :: "r"(dst), "l"(src))
#define CPCOMMIT() asm volatile("cp.async.commit_group;")
#define CPWAIT(n)  asm volatile("cp.async.wait_group %0;" :: "n"(n))

// ---------------- bf16x3 GEMM via mma.sync ----------------
// C[M,768] = A[M,768] @ B^T (+bias).  A,B bf16 hi/lo, K-major. Tile 128x128,
// K-chunk 32, 8 warps (4m x 2n, warp tile 32x64), double-buffered cp.async.
#define ROWB    80                     // padded smem row stride (64B data + 16B pad)
#define MATB    (128 * ROWB)           // 10240 B per tile
#define STAGEB  (4 * MATB)             // Ah, Al, Bh, Bl
#define SMEMB   (2 * STAGEB)           // 81920 B

__global__ void __launch_bounds__(256) gemm_mma(
    const __nv_bfloat16* __restrict__ Ah, const __nv_bfloat16* __restrict__ Al,
    const __nv_bfloat16* __restrict__ Bh, const __nv_bfloat16* __restrict__ Bl,
    float* __restrict__ C, const float* __restrict__ bias)
{
    extern __shared__ char smem[];
    const uint32_t sb = smem_u32(smem);
    const int tid  = threadIdx.x;
    const int wid  = tid >> 5;
    const int lane = tid & 31;
    const int mBase = blockIdx.y * 128;
    const int nBase = blockIdx.x * 128;
    const int warpM = (wid >> 1) * 32;       // 0,32,64,96
    const int warpN = (wid & 1) * 64;        // 0,64

    // per-thread load mapping: 2 iters x (row, 16B-seg) per matrix
    const int r0 = tid >> 2;                 // 0..63
    const int r1 = r0 + 64;                  // 64..127
    const int s4 = (tid & 3) * 8;            // bf16 elem offset of 16B seg
    const uint32_t so0 = (uint32_t)(r0 * ROWB + (tid & 3) * 16);
    const uint32_t so1 = (uint32_t)(r1 * ROWB + (tid & 3) * 16);

    const __nv_bfloat16* gAh0 = Ah + (size_t)(mBase + r0) * HIDD + s4;
    const __nv_bfloat16* gAh1 = Ah + (size_t)(mBase + r1) * HIDD + s4;
    const __nv_bfloat16* gAl0 = Al + (size_t)(mBase + r0) * HIDD + s4;
    const __nv_bfloat16* gAl1 = Al + (size_t)(mBase + r1) * HIDD + s4;
    const __nv_bfloat16* gBh0 = Bh + (size_t)(nBase + r0) * HIDD + s4;
    const __nv_bfloat16* gBh1 = Bh + (size_t)(nBase + r1) * HIDD + s4;
    const __nv_bfloat16* gBl0 = Bl + (size_t)(nBase + r0) * HIDD + s4;
    const __nv_bfloat16* gBl1 = Bl + (size_t)(nBase + r1) * HIDD + s4;

    float acc[2][8][4];
#pragma unroll
    for (int i = 0; i < 2; i++)
#pragma unroll
        for (int j = 0; j < 8; j++)
#pragma unroll
            for (int q = 0; q < 4; q++) acc[i][j][q] = 0.f;

#define ISSUE(c) do {                                                          \
    uint32_t st = sb + ((c) & 1) * STAGEB;                                     \
    int ko = (c) * 32;                                                         \
    CPA(st + so0,            gAh0 + ko); CPA(st + so1,            gAh1 + ko);  \
    CPA(st + MATB + so0,     gAl0 + ko); CPA(st + MATB + so1,     gAl1 + ko);  \
    CPA(st + 2*MATB + so0,   gBh0 + ko); CPA(st + 2*MATB + so1,   gBh1 + ko);  \
    CPA(st + 3*MATB + so0,   gBl0 + ko); CPA(st + 3*MATB + so1,   gBl1 + ko);  \
    CPCOMMIT();                                                                \
} while (0)

    ISSUE(0);
    ISSUE(1);

    // ldmatrix lane addressing (within a 16-row x 16-col bf16 tile):
    const int lrow = lane & 15;
    const int lcol = (lane >> 4) * 16;       // byte offset 0 / 16

    for (int c = 0; c < 24; c++) {
        if (c < 23) { CPWAIT(1); } else { CPWAIT(0); }
        __syncthreads();

        uint32_t st = sb + (c & 1) * STAGEB;
        uint32_t aHi = st            + (warpM + lrow) * ROWB + lcol;
        uint32_t aLo = st + MATB     + (warpM + lrow) * ROWB + lcol;
        uint32_t bHi = st + 2 * MATB + (warpN + lrow) * ROWB + lcol;
        uint32_t bLo = st + 3 * MATB + (warpN + lrow) * ROWB + lcol;

#pragma unroll
        for (int ks = 0; ks < 2; ks++) {
            uint32_t fAh[2][4], fAl[2][4], fBh[4][4], fBl[4][4];
#pragma unroll
            for (int i = 0; i < 2; i++) {
                ldm_x4(fAh[i], aHi + i * 16 * ROWB + ks * 32);
                ldm_x4(fAl[i], aLo + i * 16 * ROWB + ks * 32);
            }
#pragma unroll
            for (int j = 0; j < 4; j++) {
                ldm_x4(fBh[j], bHi + j * 16 * ROWB + ks * 32);
                ldm_x4(fBl[j], bLo + j * 16 * ROWB + ks * 32);
            }
            // ldmatrix x4 on B 16x16 tile: r0/r2 = n0-7 (k lo/hi), r1/r3 = n8-15
#pragma unroll
            for (int i = 0; i < 2; i++)
#pragma unroll
                for (int j = 0; j < 4; j++) {
                    mma_bf16(acc[i][2*j],   fAh[i], fBh[j][0], fBh[j][2]);
                    mma_bf16(acc[i][2*j+1], fAh[i], fBh[j][1], fBh[j][3]);
                    mma_bf16(acc[i][2*j],   fAl[i], fBh[j][0], fBh[j][2]);
                    mma_bf16(acc[i][2*j+1], fAl[i], fBh[j][1], fBh[j][3]);
                    mma_bf16(acc[i][2*j],   fAh[i], fBl[j][0], fBl[j][2]);
                    mma_bf16(acc[i][2*j+1], fAh[i], fBl[j][1], fBl[j][3]);
                }
        }
        __syncthreads();
        if (c + 2 < 24) ISSUE(c + 2);
    }
#undef ISSUE

    // epilogue: d-frag lane l holds rows g, g+8 (g = l>>2), cols 2t, 2t+1 (t = l&3)
    const int g = lane >> 2;
    const int t = (lane & 3) * 2;
#pragma unroll
    for (int i = 0; i < 2; i++) {
        int rowA = mBase + warpM + i * 16 + g;
        int rowB = rowA + 8;
#pragma unroll
        for (int j = 0; j < 8; j++) {
            int col = nBase + warpN + j * 8 + t;
            float b0 = 0.f, b1 = 0.f;
            if (bias) { b0 = bias[col]; b1 = bias[col + 1]; }
            *(float2*)(C + (size_t)rowA * HIDD + col) =
                make_float2(acc[i][j][0] + b0, acc[i][j][1] + b1);
            *(float2*)(C + (size_t)rowB * HIDD + col) =
                make_float2(acc[i][j][2] + b0, acc[i][j][3] + b1);
        }
    }
}

// ---------------- fp32 -> bf16 hi/lo split ----------------
__global__ __launch_bounds__(256) void cvt_hilo(
    const float4* __restrict__ src, __nv_bfloat162* __restrict__ hi,
    __nv_bfloat162* __restrict__ lo, int n4)
{
    int i = blockIdx.x * 256 + threadIdx.x;
    if (i >= n4) return;
    float4 v = src[i];
    __nv_bfloat16 h0 = __float2bfloat16(v.x);
    __nv_bfloat16 h1 = __float2bfloat16(v.y);
    __nv_bfloat16 h2 = __float2bfloat16(v.z);
    __nv_bfloat16 h3 = __float2bfloat16(v.w);
    __nv_bfloat162 a, b, c, d;
    a.x = h0; a.y = h1; b.x = h2; b.y = h3;
    c.x = __float2bfloat16(v.x - __bfloat162float(h0));
    c.y = __float2bfloat16(v.y - __bfloat162float(h1));
    d.x = __float2bfloat16(v.z - __bfloat162float(h2));
    d.y = __float2bfloat16(v.w - __bfloat162float(h3));
    hi[2 * i] = a; hi[2 * i + 1] = b;
    lo[2 * i] = c; lo[2 * i + 1] = d;
}

// ---------------- W [K,N] -> B=W^T [N,K], bf16 hi/lo ----------------
__global__ __launch_bounds__(256) void wt_cvt(
    const float* __restrict__ W, __nv_bfloat16* __restrict__ bh,
    __nv_bfloat16* __restrict__ bl)
{
    int idx = blockIdx.x * 256 + threadIdx.x;
    if (idx >= HIDD * HIDD) return;
    int n = idx / HIDD, k = idx - n * HIDD;
    float v = W[k * HIDD + n];
    __nv_bfloat16 h = __float2bfloat16(v);
    bh[idx] = h;
    bl[idx] = __float2bfloat16(v - __bfloat162float(h));
}

// ---------------- per-node per-head attention coefficients ----------------
__global__ __launch_bounds__(256) void alpha_kernel(
    const float* __restrict__ xw,
    const float* __restrict__ asrc, const float* __restrict__ adst)
{
    int gw   = (blockIdx.x * blockDim.x + threadIdx.x) >> 5;
    int lane = threadIdx.x & 31;
    if (gw >= Nn * Hh) return;
    int n = gw >> 2;
    int h = gw & 3;
    const float* row = xw + (size_t)n * HIDD + h * Dd;
    const float* a1  = asrc + h * Dd;
    const float* a2  = adst + h * Dd;
    float ss = 0.f, sd = 0.f;
#pragma unroll
    for (int k = 0; k < 6; k++) {
        float v = row[lane + 32 * k];
        ss += v * a1[lane + 32 * k];
        sd += v * a2[lane + 32 * k];
    }
#pragma unroll
    for (int o = 16; o > 0; o >>= 1) {
        ss += __shfl_xor_sync(0xffffffffu, ss, o);
        sd += __shfl_xor_sync(0xffffffffu, sd, o);
    }
    if (lane == 0) { g_as[gw] = ss; g_ad[gw] = sd; }
}

// ---------------- CSR build ----------------
__global__ void count_kernel(const int* __restrict__ ei)
{
    int i = blockIdx.x * blockDim.x + threadIdx.x;
    if (i >= E2) return;
    int d = (i < Ee) ? ei[Ee + i] : (i - Ee);
    atomicAdd(&g_deg[d], 1);
}

__global__ __launch_bounds__(1024) void scan_kernel()
{
    __shared__ int s[1024];
    int t = threadIdx.x;
    int base = t * 64;
    int sum = 0;
    for (int i = 0; i < 64; i++) sum += g_deg[base + i];
    s[t] = sum;
    __syncthreads();
    for (int off = 1; off < 1024; off <<= 1) {
        int v   = s[t];
        int add = (t >= off) ? s[t - off] : 0;
        __syncthreads();
        s[t] = v + add;
        __syncthreads();
    }
    int excl = (t == 0) ? 0 : s[t - 1];
    for (int i = 0; i < 64; i++) {
        g_off[base + i] = excl;
        excl += g_deg[base + i];
    }
    if (t == 1023) g_off[Nn] = excl;
}

__global__ void scatter_kernel(const int* __restrict__ ei)
{
    int i = blockIdx.x * blockDim.x + threadIdx.x;
    if (i >= E2) return;
    int s, d;
    if (i < Ee) { s = ei[i]; d = ei[Ee + i]; }
    else        { s = i - Ee; d = s; }
    int p = atomicAdd(&g_cur[d], 1);
    g_srcs[g_off[d] + p] = s;
}

// ---------- fused softmax-aggregate + bias + LayerNorm + ReLU + residual ----------
__global__ __launch_bounds__(128) void agg_ln_kernel(
    const float* __restrict__ xw,
    const float* __restrict__ bias_l,
    const float* __restrict__ gamma_l,
    const float* __restrict__ beta_l,
    float* __restrict__ h)
{
    int i    = blockIdx.x;
    int w    = threadIdx.x >> 5;
    int lane = threadIdx.x & 31;
    float ad = g_ad[i * Hh + w];
    int s = g_off[i], e = g_off[i + 1];
    float acc[6] = {0.f, 0.f, 0.f, 0.f, 0.f, 0.f};
    float den = 0.f;
    int cb = w * Dd + lane;

    for (int p = s; p < e; p++) {
        int j = g_srcs[p];
        float t = g_as[j * Hh + w] + ad;
        t = (t > 0.f) ? t : NEG_SLOPE * t;
        float wt = expf(t);
        den += wt;
        const float* row = xw + (size_t)j * HIDD + cb;
#pragma unroll
        for (int k = 0; k < 6; k++) acc[k] += wt * row[32 * k];
    }

    float inv = 1.f / den;
    float lsum = 0.f, lsq = 0.f;
#pragma unroll
    for (int k = 0; k < 6; k++) {
        float v = acc[k] * inv + bias_l[cb + 32 * k];
        acc[k] = v;
        lsum += v;
        lsq  += v * v;
    }
#pragma unroll
    for (int o = 16; o > 0; o >>= 1) {
        lsum += __shfl_xor_sync(0xffffffffu, lsum, o);
        lsq  += __shfl_xor_sync(0xffffffffu, lsq,  o);
    }
    __shared__ float rs[4], rq[4];
    if (lane == 0) { rs[w] = lsum; rq[w] = lsq; }
    __syncthreads();
    float tot  = rs[0] + rs[1] + rs[2] + rs[3];
    float totq = rq[0] + rq[1] + rq[2] + rq[3];
    float mean = tot * (1.f / HIDD);
    float var  = totq * (1.f / HIDD) - mean * mean;
    float rstd = rsqrtf(var + 1e-5f);

#pragma unroll
    for (int k = 0; k < 6; k++) {
        int c = cb + 32 * k;
        float v = (acc[k] - mean) * rstd * gamma_l[c] + beta_l[c];
        v = fmaxf(v, 0.f);
        size_t idx = (size_t)i * HIDD + c;
        h[idx] = v + h[idx];
    }
}

// ---------------- global mean pool ----------------
__global__ void range_init()
{
    int b = blockIdx.x * blockDim.x + threadIdx.x;
    if (b < Bb) { g_start[b] = Nn; g_end[b] = 0; }
}

__global__ void range_kernel(const int* __restrict__ bv)
{
    int n = blockIdx.x * blockDim.x + threadIdx.x;
    if (n >= Nn) return;
    int b = bv[n];
    atomicMin(&g_start[b], n);
    atomicMax(&g_end[b], n + 1);
}

__global__ __launch_bounds__(256) void pool_kernel()
{
    int b = blockIdx.x;
    int s = g_start[b], e = g_end[b];
    float cnt = (e > s) ? (float)(e - s) : 1.0f;
    float invc = 1.f / cnt;
    for (int c = threadIdx.x; c < HIDD; c += 256) {
        float sum = 0.f;
        for (int n = s; n < e; n++) sum += g_h[(size_t)n * HIDD + c];
        g_hg[(size_t)b * HIDD + c] = sum * invc;
    }
}

// ------------------------------------------------------------------------------
extern "C" void kernel_launch(void* const* d_in, const int* in_sizes, int n_in,
                              void* d_out, int out_size)
{
    const float* x       = (const float*)d_in[0];
    const int*   ei      = (const int*)  d_in[1];
    const int*   bv      = (const int*)  d_in[2];
    const float* W       = (const float*)d_in[3];
    const float* att_src = (const float*)d_in[4];
    const float* att_dst = (const float*)d_in[5];
    const float* bias    = (const float*)d_in[6];
    const float* gamma   = (const float*)d_in[7];
    const float* beta    = (const float*)d_in[8];
    const float* out_w   = (const float*)d_in[9];
    const float* out_b   = (const float*)d_in[10];
    float* out = (float*)d_out;

    float *h_p, *xw_p, *hg_p;
    int *deg_p, *cur_p;
    __nv_bfloat16 *ah_p, *al_p, *bh_p, *bl_p;
    cudaGetSymbolAddress((void**)&h_p,  g_h);
    cudaGetSymbolAddress((void**)&xw_p, g_xw);
    cudaGetSymbolAddress((void**)&hg_p, g_hg);
    cudaGetSymbolAddress((void**)&deg_p, g_deg);
    cudaGetSymbolAddress((void**)&cur_p, g_cur);
    cudaGetSymbolAddress((void**)&ah_p, g_ah);
    cudaGetSymbolAddress((void**)&al_p, g_al);
    cudaGetSymbolAddress((void**)&bh_p, g_bh);
    cudaGetSymbolAddress((void**)&bl_p, g_bl);

    cudaFuncSetAttribute(gemm_mma, cudaFuncAttributeMaxDynamicSharedMemorySize, SMEMB);

    cudaMemcpyAsync(h_p, x, (size_t)Nn * HIDD * sizeof(float),
                    cudaMemcpyDeviceToDevice);
    cudaMemsetAsync(deg_p, 0, Nn * sizeof(int));
    cudaMemsetAsync(cur_p, 0, Nn * sizeof(int));

    count_kernel  <<<(E2 + 255) / 256, 256>>>(ei);
    scan_kernel   <<<1, 1024>>>();
    scatter_kernel<<<(E2 + 255) / 256, 256>>>(ei);

    const int n4_h  = Nn * HIDD / 4;
    const int n4_hg = Bb * HIDD / 4;

    for (int l = 0; l < 2; l++) {
        cvt_hilo<<<(n4_h + 255) / 256, 256>>>((const float4*)h_p,
                                              (__nv_bfloat162*)ah_p, (__nv_bfloat162*)al_p, n4_h);
        wt_cvt<<<(HIDD * HIDD + 255) / 256, 256>>>(W + (size_t)l * HIDD * HIDD, bh_p, bl_p);
        gemm_mma<<<dim3(HIDD / 128, Nn / 128), 256, SMEMB>>>(ah_p, al_p, bh_p, bl_p,
                                                             xw_p, nullptr);
        alpha_kernel<<<(Nn * Hh) / 8, 256>>>(xw_p,
                                             att_src + l * Hh * Dd,
                                             att_dst + l * Hh * Dd);
        agg_ln_kernel<<<Nn, 128>>>(xw_p, bias + l * HIDD,
                                   gamma + l * HIDD, beta + l * HIDD, h_p);
    }

    range_init <<<Bb / 256, 256>>>();
    range_kernel<<<Nn / 256, 256>>>(bv);
    pool_kernel <<<Bb, 256>>>();

    cvt_hilo<<<(n4_hg + 255) / 256, 256>>>((const float4*)hg_p,
                                           (__nv_bfloat162*)ah_p, (__nv_bfloat162*)al_p, n4_hg);
    wt_cvt<<<(HIDD * HIDD + 255) / 256, 256>>>(out_w, bh_p, bl_p);
    gemm_mma<<<dim3(HIDD / 128, Bb / 128), 256, SMEMB>>>(ah_p, al_p, bh_p, bl_p, out, out_b);
}

// round 6
// speedup vs baseline: 1.9211x; 1.0139x over previous
#include <cuda_runtime.h>
#include <cuda_bf16.h>
#include <math.h>
#include <stdint.h>

#define Nn   65536
#define Ee   262144
#define E2   327680
#define Bb   2048
#define Hh   4
#define Dd   192
#define HIDD 768
#define NEG_SLOPE 0.2f

// ---------------- device scratch ----------------
__device__ float g_h [(size_t)Nn * HIDD];
__device__ float g_xw[(size_t)Nn * HIDD];
__device__ float g_as[Nn * Hh];
__device__ float g_ad[Nn * Hh];
__device__ int   g_deg[Nn];
__device__ int   g_off[Nn + 1];
__device__ int   g_cur[Nn];
__device__ int   g_srcs[E2];
__device__ int   g_start[Bb];
__device__ int   g_end[Bb];
__device__ __nv_bfloat16 g_ah[(size_t)Nn * HIDD];   // A hi
__device__ __nv_bfloat16 g_al[(size_t)Nn * HIDD];   // A lo
__device__ __nv_bfloat16 g_bh[HIDD * HIDD];         // B (=W^T) hi
__device__ __nv_bfloat16 g_bl[HIDD * HIDD];         // B lo

// ---------------- helpers ----------------
__device__ __forceinline__ uint32_t smem_u32(const void* p) {
    uint32_t a;
    asm("{ .reg .u64 t; cvta.to.shared.u64 t, %1; cvt.u32.u64 %0, t; }" : "=r"(a) : "l"(p));
    return a;
}

__device__ __forceinline__ void ldm_x4(uint32_t* r, uint32_t addr) {
    asm volatile("ldmatrix.sync.aligned.m8n8.x4.shared.b16 {%0,%1,%2,%3}, [%4];"
        : "=r"(r[0]), "=r"(r[1]), "=r"(r[2]), "=r"(r[3]) : "r"(addr));
}

__device__ __forceinline__ void mma_bf16(float* d, const uint32_t* a, uint32_t b0, uint32_t b1) {
    asm volatile("mma.sync.aligned.m16n8k16.row.col.f32.bf16.bf16.f32 "
        "{%0,%1,%2,%3}, {%4,%5,%6,%7}, {%8,%9}, {%0,%1,%2,%3};"
        : "+f"(d[0]), "+f"(d[1]), "+f"(d[2]), "+f"(d[3])
        : "r"(a[0]), "r"(a[1]), "r"(a[2]), "r"(a[3]), "r"(b0), "r"(b1));
}

#define CPA(dst, src) \
    asm volatile("cp.async.cg.shared.global [%0], [%1], 16;" :: "r"(dst), "l"(src))
#define CPCOMMIT() asm volatile("cp.async.commit_group;")
#define CPWAIT(n)  asm volatile("cp.async.wait_group %0;" :: "n"(n))

__device__ __forceinline__ void split_bf16(float v, __nv_bfloat16& h, __nv_bfloat16& l) {
    h = __float2bfloat16(v);
    l = __float2bfloat16(v - __bfloat162float(h));
}

// ---------------- bf16x3 GEMM via mma.sync ----------------
// C[M,768] = A[M,768] @ B^T (+bias).  Tile 128x128, K-chunk 64, 3-stage
// cp.async pipeline (single barrier per chunk), 8 warps (4m x 2n).
#define ROWB    144                    // padded smem row stride (128B data + 16B pad)
#define MATB    (128 * ROWB)           // 18432 B per tile
#define STAGEB  (4 * MATB)             // Ah, Al, Bh, Bl = 73728 B
#define NCHUNK  12
#define SMEMB   (3 * STAGEB)           // 221184 B

__global__ void __launch_bounds__(256) gemm_mma(
    const __nv_bfloat16* __restrict__ Ah, const __nv_bfloat16* __restrict__ Al,
    const __nv_bfloat16* __restrict__ Bh, const __nv_bfloat16* __restrict__ Bl,
    float* __restrict__ C, const float* __restrict__ bias)
{
    extern __shared__ char smem[];
    const uint32_t sb = smem_u32(smem);
    const int tid  = threadIdx.x;
    const int wid  = tid >> 5;
    const int lane = tid & 31;
    const int mBase = blockIdx.y * 128;
    const int nBase = blockIdx.x * 128;
    const int warpM = (wid >> 1) * 32;       // 0,32,64,96
    const int warpN = (wid & 1) * 64;        // 0,64

    // load mapping: thread handles rows r0+32t (t=0..3), 16B segment (tid&7)
    const int r0 = tid >> 3;                 // 0..31
    const int c8 = (tid & 7) * 8;            // bf16 elem offset
    const uint32_t so = (uint32_t)(r0 * ROWB + (tid & 7) * 16);

    const __nv_bfloat16* pAh = Ah + (size_t)(mBase + r0) * HIDD + c8;
    const __nv_bfloat16* pAl = Al + (size_t)(mBase + r0) * HIDD + c8;
    const __nv_bfloat16* pBh = Bh + (size_t)(nBase + r0) * HIDD + c8;
    const __nv_bfloat16* pBl = Bl + (size_t)(nBase + r0) * HIDD + c8;

    float acc[2][8][4];
#pragma unroll
    for (int i = 0; i < 2; i++)
#pragma unroll
        for (int j = 0; j < 8; j++)
#pragma unroll
            for (int q = 0; q < 4; q++) acc[i][j][q] = 0.f;

#define ISSUE(c) do {                                                           \
    uint32_t st = sb + ((c) % 3) * STAGEB;                                      \
    int ko = (c) * 64;                                                          \
    _Pragma("unroll")                                                           \
    for (int t = 0; t < 4; t++) {                                               \
        uint32_t o = so + t * 32 * ROWB;                                        \
        size_t  go = (size_t)t * 32 * HIDD + ko;                                \
        CPA(st + o,            pAh + go);                                       \
        CPA(st + MATB + o,     pAl + go);                                       \
        CPA(st + 2*MATB + o,   pBh + go);                                       \
        CPA(st + 3*MATB + o,   pBl + go);                                       \
    }                                                                           \
    CPCOMMIT();                                                                 \
} while (0)

    ISSUE(0);
    ISSUE(1);

    const int lrow = lane & 15;
    const int lcol = (lane >> 4) * 16;       // byte offset 0 / 16

    for (int c = 0; c < NCHUNK; c++) {
        if (c == NCHUNK - 1) { CPWAIT(0); } else { CPWAIT(1); }
        __syncthreads();
        if (c + 2 < NCHUNK) ISSUE(c + 2);    // stage (c+2)%3 was consumed at c-1

        uint32_t st = sb + (c % 3) * STAGEB;
        uint32_t aHi = st            + (warpM + lrow) * ROWB + lcol;
        uint32_t aLo = st + MATB     + (warpM + lrow) * ROWB + lcol;
        uint32_t bHi = st + 2 * MATB + (warpN + lrow) * ROWB + lcol;
        uint32_t bLo = st + 3 * MATB + (warpN + lrow) * ROWB + lcol;

#pragma unroll
        for (int ks = 0; ks < 4; ks++) {
            uint32_t fAh[2][4], fAl[2][4], fBh[4][4], fBl[4][4];
#pragma unroll
            for (int i = 0; i < 2; i++) {
                ldm_x4(fAh[i], aHi + i * 16 * ROWB + ks * 32);
                ldm_x4(fAl[i], aLo + i * 16 * ROWB + ks * 32);
            }
#pragma unroll
            for (int j = 0; j < 4; j++) {
                ldm_x4(fBh[j], bHi + j * 16 * ROWB + ks * 32);
                ldm_x4(fBl[j], bLo + j * 16 * ROWB + ks * 32);
            }
#pragma unroll
            for (int i = 0; i < 2; i++)
#pragma unroll
                for (int j = 0; j < 4; j++) {
                    mma_bf16(acc[i][2*j],   fAh[i], fBh[j][0], fBh[j][2]);
                    mma_bf16(acc[i][2*j+1], fAh[i], fBh[j][1], fBh[j][3]);
                    mma_bf16(acc[i][2*j],   fAl[i], fBh[j][0], fBh[j][2]);
                    mma_bf16(acc[i][2*j+1], fAl[i], fBh[j][1], fBh[j][3]);
                    mma_bf16(acc[i][2*j],   fAh[i], fBl[j][0], fBl[j][2]);
                    mma_bf16(acc[i][2*j+1], fAh[i], fBl[j][1], fBl[j][3]);
                }
        }
    }
#undef ISSUE

    // epilogue: d-frag lane l holds rows g, g+8 (g = l>>2), cols 2t, 2t+1 (t = l&3)
    const int g = lane >> 2;
    const int t = (lane & 3) * 2;
#pragma unroll
    for (int i = 0; i < 2; i++) {
        int rowA = mBase + warpM + i * 16 + g;
        int rowB = rowA + 8;
#pragma unroll
        for (int j = 0; j < 8; j++) {
            int col = nBase + warpN + j * 8 + t;
            float b0 = 0.f, b1 = 0.f;
            if (bias) { b0 = bias[col]; b1 = bias[col + 1]; }
            *(float2*)(C + (size_t)rowA * HIDD + col) =
                make_float2(acc[i][j][0] + b0, acc[i][j][1] + b1);
            *(float2*)(C + (size_t)rowB * HIDD + col) =
                make_float2(acc[i][j][2] + b0, acc[i][j][3] + b1);
        }
    }
}

// ---------------- init: h = x, plus bf16 hi/lo split ----------------
__global__ __launch_bounds__(256) void init_cvt(
    const float4* __restrict__ src, float4* __restrict__ hcopy,
    __nv_bfloat162* __restrict__ hi, __nv_bfloat162* __restrict__ lo, int n4)
{
    int i = blockIdx.x * 256 + threadIdx.x;
    if (i >= n4) return;
    float4 v = src[i];
    hcopy[i] = v;
    __nv_bfloat162 a, b, c, d;
    split_bf16(v.x, a.x, c.x);
    split_bf16(v.y, a.y, c.y);
    split_bf16(v.z, b.x, d.x);
    split_bf16(v.w, b.y, d.y);
    hi[2 * i] = a; hi[2 * i + 1] = b;
    lo[2 * i] = c; lo[2 * i + 1] = d;
}

// ---------------- W [K,N] -> B=W^T [N,K], bf16 hi/lo ----------------
__global__ __launch_bounds__(256) void wt_cvt(
    const float* __restrict__ W, __nv_bfloat16* __restrict__ bh,
    __nv_bfloat16* __restrict__ bl)
{
    int idx = blockIdx.x * 256 + threadIdx.x;
    if (idx >= HIDD * HIDD) return;
    int n = idx / HIDD, k = idx - n * HIDD;
    float v = W[k * HIDD + n];
    split_bf16(v, bh[idx], bl[idx]);
}

// ---------------- per-node per-head attention coefficients ----------------
__global__ __launch_bounds__(256) void alpha_kernel(
    const float* __restrict__ xw,
    const float* __restrict__ asrc, const float* __restrict__ adst)
{
    int gw   = (blockIdx.x * blockDim.x + threadIdx.x) >> 5;
    int lane = threadIdx.x & 31;
    if (gw >= Nn * Hh) return;
    int n = gw >> 2;
    int h = gw & 3;
    const float* row = xw + (size_t)n * HIDD + h * Dd;
    const float* a1  = asrc + h * Dd;
    const float* a2  = adst + h * Dd;
    float ss = 0.f, sd = 0.f;
#pragma unroll
    for (int k = 0; k < 6; k++) {
        float v = row[lane + 32 * k];
        ss += v * a1[lane + 32 * k];
        sd += v * a2[lane + 32 * k];
    }
#pragma unroll
    for (int o = 16; o > 0; o >>= 1) {
        ss += __shfl_xor_sync(0xffffffffu, ss, o);
        sd += __shfl_xor_sync(0xffffffffu, sd, o);
    }
    if (lane == 0) { g_as[gw] = ss; g_ad[gw] = sd; }
}

// ---------------- CSR build ----------------
__global__ void count_kernel(const int* __restrict__ ei)
{
    int i = blockIdx.x * blockDim.x + threadIdx.x;
    if (i >= E2) return;
    int d = (i < Ee) ? ei[Ee + i] : (i - Ee);
    atomicAdd(&g_deg[d], 1);
}

__global__ __launch_bounds__(1024) void scan_kernel()
{
    __shared__ int s[1024];
    int t = threadIdx.x;
    int base = t * 64;
    int sum = 0;
    for (int i = 0; i < 64; i++) sum += g_deg[base + i];
    s[t] = sum;
    __syncthreads();
    for (int off = 1; off < 1024; off <<= 1) {
        int v   = s[t];
        int add = (t >= off) ? s[t - off] : 0;
        __syncthreads();
        s[t] = v + add;
        __syncthreads();
    }
    int excl = (t == 0) ? 0 : s[t - 1];
    for (int i = 0; i < 64; i++) {
        g_off[base + i] = excl;
        excl += g_deg[base + i];
    }
    if (t == 1023) g_off[Nn] = excl;
}

__global__ void scatter_kernel(const int* __restrict__ ei)
{
    int i = blockIdx.x * blockDim.x + threadIdx.x;
    if (i >= E2) return;
    int s, d;
    if (i < Ee) { s = ei[i]; d = ei[Ee + i]; }
    else        { s = i - Ee; d = s; }
    int p = atomicAdd(&g_cur[d], 1);
    g_srcs[g_off[d] + p] = s;
}

// ---------- fused softmax-aggregate + bias + LayerNorm + ReLU + residual ----------
// Optionally emits bf16 hi/lo of the new h for the next layer's GEMM.
__global__ __launch_bounds__(128) void agg_ln_kernel(
    const float* __restrict__ xw,
    const float* __restrict__ bias_l,
    const float* __restrict__ gamma_l,
    const float* __restrict__ beta_l,
    float* __restrict__ h,
    __nv_bfloat16* __restrict__ oh,
    __nv_bfloat16* __restrict__ ol)
{
    int i    = blockIdx.x;
    int w    = threadIdx.x >> 5;
    int lane = threadIdx.x & 31;
    float ad = g_ad[i * Hh + w];
    int s = g_off[i], e = g_off[i + 1];
    float acc[6] = {0.f, 0.f, 0.f, 0.f, 0.f, 0.f};
    float den = 0.f;
    int cb = w * Dd + lane;

    for (int p = s; p < e; p++) {
        int j = g_srcs[p];
        float t = g_as[j * Hh + w] + ad;
        t = (t > 0.f) ? t : NEG_SLOPE * t;
        float wt = expf(t);
        den += wt;
        const float* row = xw + (size_t)j * HIDD + cb;
#pragma unroll
        for (int k = 0; k < 6; k++) acc[k] += wt * row[32 * k];
    }

    float inv = 1.f / den;
    float lsum = 0.f, lsq = 0.f;
#pragma unroll
    for (int k = 0; k < 6; k++) {
        float v = acc[k] * inv + bias_l[cb + 32 * k];
        acc[k] = v;
        lsum += v;
        lsq  += v * v;
    }
#pragma unroll
    for (int o = 16; o > 0; o >>= 1) {
        lsum += __shfl_xor_sync(0xffffffffu, lsum, o);
        lsq  += __shfl_xor_sync(0xffffffffu, lsq,  o);
    }
    __shared__ float rs[4], rq[4];
    if (lane == 0) { rs[w] = lsum; rq[w] = lsq; }
    __syncthreads();
    float tot  = rs[0] + rs[1] + rs[2] + rs[3];
    float totq = rq[0] + rq[1] + rq[2] + rq[3];
    float mean = tot * (1.f / HIDD);
    float var  = totq * (1.f / HIDD) - mean * mean;
    float rstd = rsqrtf(var + 1e-5f);

#pragma unroll
    for (int k = 0; k < 6; k++) {
        int c = cb + 32 * k;
        float v = (acc[k] - mean) * rstd * gamma_l[c] + beta_l[c];
        v = fmaxf(v, 0.f);
        size_t idx = (size_t)i * HIDD + c;
        float nh = v + h[idx];
        h[idx] = nh;
        if (oh) {
            __nv_bfloat16 hh, ll;
            split_bf16(nh, hh, ll);
            oh[idx] = hh;
            ol[idx] = ll;
        }
    }
}

// ---------------- global mean pool (emits bf16 hi/lo directly) ----------------
__global__ void range_init()
{
    int b = blockIdx.x * blockDim.x + threadIdx.x;
    if (b < Bb) { g_start[b] = Nn; g_end[b] = 0; }
}

__global__ void range_kernel(const int* __restrict__ bv)
{
    int n = blockIdx.x * blockDim.x + threadIdx.x;
    if (n >= Nn) return;
    int b = bv[n];
    atomicMin(&g_start[b], n);
    atomicMax(&g_end[b], n + 1);
}

__global__ __launch_bounds__(256) void pool_kernel(
    __nv_bfloat16* __restrict__ oh, __nv_bfloat16* __restrict__ ol)
{
    int b = blockIdx.x;
    int s = g_start[b], e = g_end[b];
    float cnt = (e > s) ? (float)(e - s) : 1.0f;
    float invc = 1.f / cnt;
    for (int c = threadIdx.x; c < HIDD; c += 256) {
        float sum = 0.f;
        for (int n = s; n < e; n++) sum += g_h[(size_t)n * HIDD + c];
        float v = sum * invc;
        size_t idx = (size_t)b * HIDD + c;
        __nv_bfloat16 hh, ll;
        split_bf16(v, hh, ll);
        oh[idx] = hh;
        ol[idx] = ll;
    }
}

// ------------------------------------------------------------------------------
extern "C" void kernel_launch(void* const* d_in, const int* in_sizes, int n_in,
                              void* d_out, int out_size)
{
    const float* x       = (const float*)d_in[0];
    const int*   ei      = (const int*)  d_in[1];
    const int*   bv      = (const int*)  d_in[2];
    const float* W       = (const float*)d_in[3];
    const float* att_src = (const float*)d_in[4];
    const float* att_dst = (const float*)d_in[5];
    const float* bias    = (const float*)d_in[6];
    const float* gamma   = (const float*)d_in[7];
    const float* beta    = (const float*)d_in[8];
    const float* out_w   = (const float*)d_in[9];
    const float* out_b   = (const float*)d_in[10];
    float* out = (float*)d_out;

    float *h_p, *xw_p;
    int *deg_p, *cur_p;
    __nv_bfloat16 *ah_p, *al_p, *bh_p, *bl_p;
    cudaGetSymbolAddress((void**)&h_p,  g_h);
    cudaGetSymbolAddress((void**)&xw_p, g_xw);
    cudaGetSymbolAddress((void**)&deg_p, g_deg);
    cudaGetSymbolAddress((void**)&cur_p, g_cur);
    cudaGetSymbolAddress((void**)&ah_p, g_ah);
    cudaGetSymbolAddress((void**)&al_p, g_al);
    cudaGetSymbolAddress((void**)&bh_p, g_bh);
    cudaGetSymbolAddress((void**)&bl_p, g_bl);

    cudaFuncSetAttribute(gemm_mma, cudaFuncAttributeMaxDynamicSharedMemorySize, SMEMB);

    cudaMemsetAsync(deg_p, 0, Nn * sizeof(int));
    cudaMemsetAsync(cur_p, 0, Nn * sizeof(int));

    const int n4_h = Nn * HIDD / 4;
    init_cvt<<<(n4_h + 255) / 256, 256>>>((const float4*)x, (float4*)h_p,
                                          (__nv_bfloat162*)ah_p, (__nv_bfloat162*)al_p, n4_h);

    count_kernel  <<<(E2 + 255) / 256, 256>>>(ei);
    scan_kernel   <<<1, 1024>>>();
    scatter_kernel<<<(E2 + 255) / 256, 256>>>(ei);

    for (int l = 0; l < 2; l++) {
        wt_cvt<<<(HIDD * HIDD + 255) / 256, 256>>>(W + (size_t)l * HIDD * HIDD, bh_p, bl_p);
        gemm_mma<<<dim3(HIDD / 128, Nn / 128), 256, SMEMB>>>(ah_p, al_p, bh_p, bl_p,
                                                             xw_p, nullptr);
        alpha_kernel<<<(Nn * Hh) / 8, 256>>>(xw_p,
                                             att_src + l * Hh * Dd,
                                             att_dst + l * Hh * Dd);
        agg_ln_kernel<<<Nn, 128>>>(xw_p, bias + l * HIDD,
                                   gamma + l * HIDD, beta + l * HIDD, h_p,
                                   (l == 0) ? ah_p : (__nv_bfloat16*)nullptr,
                                   (l == 0) ? al_p : (__nv_bfloat16*)nullptr);
    }

    range_init <<<Bb / 256, 256>>>();
    range_kernel<<<Nn / 256, 256>>>(bv);
    pool_kernel <<<Bb, 256>>>(ah_p, al_p);

    wt_cvt<<<(HIDD * HIDD + 255) / 256, 256>>>(out_w, bh_p, bl_p);
    gemm_mma<<<dim3(HIDD / 128, Bb / 128), 256, SMEMB>>>(ah_p, al_p, bh_p, bl_p, out, out_b);
}

// round 7
// speedup vs baseline: 1.9235x; 1.0013x over previous
#include <cuda_runtime.h>
#include <cuda_bf16.h>
#include <math.h>
#include <stdint.h>

#define Nn   65536
#define Ee   262144
#define E2   327680
#define Bb   2048
#define Hh   4
#define Dd   192
#define HIDD 768
#define NEG_SLOPE 0.2f

// ---------------- device scratch ----------------
__device__ float g_h [(size_t)Nn * HIDD];
__device__ float g_xw[(size_t)Nn * HIDD];
__device__ float g_as[Nn * Hh];
__device__ float g_ad[Nn * Hh];
__device__ int   g_deg[Nn];
__device__ int   g_off[Nn + 1];
__device__ int   g_cur[Nn];
__device__ int   g_srcs[E2];
__device__ int   g_start[Bb];
__device__ int   g_end[Bb];
__device__ __nv_bfloat16 g_ah[(size_t)Nn * HIDD];   // A hi
__device__ __nv_bfloat16 g_al[(size_t)Nn * HIDD];   // A lo
__device__ __nv_bfloat16 g_bh[HIDD * HIDD];         // B (=W^T) hi
__device__ __nv_bfloat16 g_bl[HIDD * HIDD];         // B lo

// ---------------- helpers ----------------
__device__ __forceinline__ uint32_t smem_u32(const void* p) {
    uint32_t a;
    asm("{ .reg .u64 t; cvta.to.shared.u64 t, %1; cvt.u32.u64 %0, t; }" : "=r"(a) : "l"(p));
    return a;
}

__device__ __forceinline__ void ldm_x4(uint32_t* r, uint32_t addr) {
    asm volatile("ldmatrix.sync.aligned.m8n8.x4.shared.b16 {%0,%1,%2,%3}, [%4];"
        : "=r"(r[0]), "=r"(r[1]), "=r"(r[2]), "=r"(r[3]) : "r"(addr));
}

// NOTE: non-volatile — register-only op, lets the compiler schedule freely.
__device__ __forceinline__ void mma_bf16(float* d, const uint32_t* a, uint32_t b0, uint32_t b1) {
    asm("mma.sync.aligned.m16n8k16.row.col.f32.bf16.bf16.f32 "
        "{%0,%1,%2,%3}, {%4,%5,%6,%7}, {%8,%9}, {%0,%1,%2,%3};"
        : "+f"(d[0]), "+f"(d[1]), "+f"(d[2]), "+f"(d[3])
        : "r"(a[0]), "r"(a[1]), "r"(a[2]), "r"(a[3]), "r"(b0), "r"(b1));
}

#define CPA(dst, src) \
    asm volatile("cp.async.cg.shared.global [%0], [%1], 16;" :: "r"(dst), "l"(src))
#define CPCOMMIT() asm volatile("cp.async.commit_group;")
#define CPWAIT(n)  asm volatile("cp.async.wait_group %0;" :: "n"(n))

__device__ __forceinline__ void split_bf16(float v, __nv_bfloat16& h, __nv_bfloat16& l) {
    h = __float2bfloat16(v);
    l = __float2bfloat16(v - __bfloat162float(h));
}

// ---------------- bf16x3 GEMM via mma.sync ----------------
// C[M,768] = A[M,768] @ B^T (+bias).  Tile 128x128, K-chunk 64, 3-stage
// cp.async pipeline, 8 warps (4m x 2n). MMAs are PASS-MAJOR so dependent
// writes to the same accumulator are 16 MMAs apart (covers HMMA latency).
#define ROWB    144                    // padded smem row stride (128B data + 16B pad)
#define MATB    (128 * ROWB)           // 18432 B per tile
#define STAGEB  (4 * MATB)             // Ah, Al, Bh, Bl = 73728 B
#define NCHUNK  12
#define SMEMB   (3 * STAGEB)           // 221184 B

__global__ void __launch_bounds__(256) gemm_mma(
    const __nv_bfloat16* __restrict__ Ah, const __nv_bfloat16* __restrict__ Al,
    const __nv_bfloat16* __restrict__ Bh, const __nv_bfloat16* __restrict__ Bl,
    float* __restrict__ C, const float* __restrict__ bias)
{
    extern __shared__ char smem[];
    const uint32_t sb = smem_u32(smem);
    const int tid  = threadIdx.x;
    const int wid  = tid >> 5;
    const int lane = tid & 31;
    const int mBase = blockIdx.y * 128;
    const int nBase = blockIdx.x * 128;
    const int warpM = (wid >> 1) * 32;       // 0,32,64,96
    const int warpN = (wid & 1) * 64;        // 0,64

    const int r0 = tid >> 3;                 // 0..31
    const int c8 = (tid & 7) * 8;            // bf16 elem offset
    const uint32_t so = (uint32_t)(r0 * ROWB + (tid & 7) * 16);

    const __nv_bfloat16* pAh = Ah + (size_t)(mBase + r0) * HIDD + c8;
    const __nv_bfloat16* pAl = Al + (size_t)(mBase + r0) * HIDD + c8;
    const __nv_bfloat16* pBh = Bh + (size_t)(nBase + r0) * HIDD + c8;
    const __nv_bfloat16* pBl = Bl + (size_t)(nBase + r0) * HIDD + c8;

    float acc[2][8][4];
#pragma unroll
    for (int i = 0; i < 2; i++)
#pragma unroll
        for (int j = 0; j < 8; j++)
#pragma unroll
            for (int q = 0; q < 4; q++) acc[i][j][q] = 0.f;

#define ISSUE(c) do {                                                           \
    uint32_t st = sb + ((c) % 3) * STAGEB;                                      \
    int ko = (c) * 64;                                                          \
    _Pragma("unroll")                                                           \
    for (int t = 0; t < 4; t++) {                                               \
        uint32_t o = so + t * 32 * ROWB;                                        \
        size_t  go = (size_t)t * 32 * HIDD + ko;                                \
        CPA(st + o,            pAh + go);                                       \
        CPA(st + MATB + o,     pAl + go);                                       \
        CPA(st + 2*MATB + o,   pBh + go);                                       \
        CPA(st + 3*MATB + o,   pBl + go);                                       \
    }                                                                           \
    CPCOMMIT();                                                                 \
} while (0)

    ISSUE(0);
    ISSUE(1);

    const int lrow = lane & 15;
    const int lcol = (lane >> 4) * 16;       // byte offset 0 / 16

    for (int c = 0; c < NCHUNK; c++) {
        if (c == NCHUNK - 1) { CPWAIT(0); } else { CPWAIT(1); }
        __syncthreads();
        if (c + 2 < NCHUNK) ISSUE(c + 2);

        uint32_t st = sb + (c % 3) * STAGEB;
        uint32_t aHi = st            + (warpM + lrow) * ROWB + lcol;
        uint32_t aLo = st + MATB     + (warpM + lrow) * ROWB + lcol;
        uint32_t bHi = st + 2 * MATB + (warpN + lrow) * ROWB + lcol;
        uint32_t bLo = st + 3 * MATB + (warpN + lrow) * ROWB + lcol;

#pragma unroll
        for (int ks = 0; ks < 4; ks++) {
            uint32_t fAh[2][4], fAl[2][4], fBh[4][4], fBl[4][4];
#pragma unroll
            for (int i = 0; i < 2; i++) {
                ldm_x4(fAh[i], aHi + i * 16 * ROWB + ks * 32);
                ldm_x4(fAl[i], aLo + i * 16 * ROWB + ks * 32);
            }
#pragma unroll
            for (int j = 0; j < 4; j++) {
                ldm_x4(fBh[j], bHi + j * 16 * ROWB + ks * 32);
                ldm_x4(fBl[j], bLo + j * 16 * ROWB + ks * 32);
            }
            // pass 1: Ah * Bh  (16 independent accumulators)
#pragma unroll
            for (int i = 0; i < 2; i++)
#pragma unroll
                for (int j = 0; j < 4; j++) {
                    mma_bf16(acc[i][2*j],   fAh[i], fBh[j][0], fBh[j][2]);
                    mma_bf16(acc[i][2*j+1], fAh[i], fBh[j][1], fBh[j][3]);
                }
            // pass 2: Al * Bh
#pragma unroll
            for (int i = 0; i < 2; i++)
#pragma unroll
                for (int j = 0; j < 4; j++) {
                    mma_bf16(acc[i][2*j],   fAl[i], fBh[j][0], fBh[j][2]);
                    mma_bf16(acc[i][2*j+1], fAl[i], fBh[j][1], fBh[j][3]);
                }
            // pass 3: Ah * Bl
#pragma unroll
            for (int i = 0; i < 2; i++)
#pragma unroll
                for (int j = 0; j < 4; j++) {
                    mma_bf16(acc[i][2*j],   fAh[i], fBl[j][0], fBl[j][2]);
                    mma_bf16(acc[i][2*j+1], fAh[i], fBl[j][1], fBl[j][3]);
                }
        }
    }
#undef ISSUE

    // epilogue: d-frag lane l holds rows g, g+8 (g = l>>2), cols 2t, 2t+1 (t = l&3)
    const int g = lane >> 2;
    const int t = (lane & 3) * 2;
#pragma unroll
    for (int i = 0; i < 2; i++) {
        int rowA = mBase + warpM + i * 16 + g;
        int rowB = rowA + 8;
#pragma unroll
        for (int j = 0; j < 8; j++) {
            int col = nBase + warpN + j * 8 + t;
            float b0 = 0.f, b1 = 0.f;
            if (bias) { b0 = bias[col]; b1 = bias[col + 1]; }
            *(float2*)(C + (size_t)rowA * HIDD + col) =
                make_float2(acc[i][j][0] + b0, acc[i][j][1] + b1);
            *(float2*)(C + (size_t)rowB * HIDD + col) =
                make_float2(acc[i][j][2] + b0, acc[i][j][3] + b1);
        }
    }
}

// ---------------- init: h = x, plus bf16 hi/lo split ----------------
__global__ __launch_bounds__(256) void init_cvt(
    const float4* __restrict__ src, float4* __restrict__ hcopy,
    __nv_bfloat162* __restrict__ hi, __nv_bfloat162* __restrict__ lo, int n4)
{
    int i = blockIdx.x * 256 + threadIdx.x;
    if (i >= n4) return;
    float4 v = src[i];
    hcopy[i] = v;
    __nv_bfloat162 a, b, c, d;
    split_bf16(v.x, a.x, c.x);
    split_bf16(v.y, a.y, c.y);
    split_bf16(v.z, b.x, d.x);
    split_bf16(v.w, b.y, d.y);
    hi[2 * i] = a; hi[2 * i + 1] = b;
    lo[2 * i] = c; lo[2 * i + 1] = d;
}

// ---------------- W [K,N] -> B=W^T [N,K], bf16 hi/lo ----------------
__global__ __launch_bounds__(256) void wt_cvt(
    const float* __restrict__ W, __nv_bfloat16* __restrict__ bh,
    __nv_bfloat16* __restrict__ bl)
{
    int idx = blockIdx.x * 256 + threadIdx.x;
    if (idx >= HIDD * HIDD) return;
    int n = idx / HIDD, k = idx - n * HIDD;
    float v = W[k * HIDD + n];
    split_bf16(v, bh[idx], bl[idx]);
}

// ---------------- per-node per-head attention coefficients ----------------
__global__ __launch_bounds__(256) void alpha_kernel(
    const float* __restrict__ xw,
    const float* __restrict__ asrc, const float* __restrict__ adst)
{
    int gw   = (blockIdx.x * blockDim.x + threadIdx.x) >> 5;
    int lane = threadIdx.x & 31;
    if (gw >= Nn * Hh) return;
    int n = gw >> 2;
    int h = gw & 3;
    const float* row = xw + (size_t)n * HIDD + h * Dd;
    const float* a1  = asrc + h * Dd;
    const float* a2  = adst + h * Dd;
    float ss = 0.f, sd = 0.f;
#pragma unroll
    for (int k = 0; k < 6; k++) {
        float v = row[lane + 32 * k];
        ss += v * a1[lane + 32 * k];
        sd += v * a2[lane + 32 * k];
    }
#pragma unroll
    for (int o = 16; o > 0; o >>= 1) {
        ss += __shfl_xor_sync(0xffffffffu, ss, o);
        sd += __shfl_xor_sync(0xffffffffu, sd, o);
    }
    if (lane == 0) { g_as[gw] = ss; g_ad[gw] = sd; }
}

// ---------------- CSR build ----------------
__global__ void count_kernel(const int* __restrict__ ei)
{
    int i = blockIdx.x * blockDim.x + threadIdx.x;
    if (i >= E2) return;
    int d = (i < Ee) ? ei[Ee + i] : (i - Ee);
    atomicAdd(&g_deg[d], 1);
}

__global__ __launch_bounds__(1024) void scan_kernel()
{
    __shared__ int s[1024];
    int t = threadIdx.x;
    int base = t * 64;
    int sum = 0;
    for (int i = 0; i < 64; i++) sum += g_deg[base + i];
    s[t] = sum;
    __syncthreads();
    for (int off = 1; off < 1024; off <<= 1) {
        int v   = s[t];
        int add = (t >= off) ? s[t - off] : 0;
        __syncthreads();
        s[t] = v + add;
        __syncthreads();
    }
    int excl = (t == 0) ? 0 : s[t - 1];
    for (int i = 0; i < 64; i++) {
        g_off[base + i] = excl;
        excl += g_deg[base + i];
    }
    if (t == 1023) g_off[Nn] = excl;
}

__global__ void scatter_kernel(const int* __restrict__ ei)
{
    int i = blockIdx.x * blockDim.x + threadIdx.x;
    if (i >= E2) return;
    int s, d;
    if (i < Ee) { s = ei[i]; d = ei[Ee + i]; }
    else        { s = i - Ee; d = s; }
    int p = atomicAdd(&g_cur[d], 1);
    g_srcs[g_off[d] + p] = s;
}

// ---------- fused softmax-aggregate + bias + LayerNorm + ReLU + residual ----------
__global__ __launch_bounds__(128) void agg_ln_kernel(
    const float* __restrict__ xw,
    const float* __restrict__ bias_l,
    const float* __restrict__ gamma_l,
    const float* __restrict__ beta_l,
    float* __restrict__ h,
    __nv_bfloat16* __restrict__ oh,
    __nv_bfloat16* __restrict__ ol)
{
    int i    = blockIdx.x;
    int w    = threadIdx.x >> 5;
    int lane = threadIdx.x & 31;
    float ad = g_ad[i * Hh + w];
    int s = g_off[i], e = g_off[i + 1];
    float acc[6] = {0.f, 0.f, 0.f, 0.f, 0.f, 0.f};
    float den = 0.f;
    int cb = w * Dd + lane;

    for (int p = s; p < e; p++) {
        int j = g_srcs[p];
        float t = g_as[j * Hh + w] + ad;
        t = (t > 0.f) ? t : NEG_SLOPE * t;
        float wt = expf(t);
        den += wt;
        const float* row = xw + (size_t)j * HIDD + cb;
#pragma unroll
        for (int k = 0; k < 6; k++) acc[k] += wt * row[32 * k];
    }

    float inv = 1.f / den;
    float lsum = 0.f, lsq = 0.f;
#pragma unroll
    for (int k = 0; k < 6; k++) {
        float v = acc[k] * inv + bias_l[cb + 32 * k];
        acc[k] = v;
        lsum += v;
        lsq  += v * v;
    }
#pragma unroll
    for (int o = 16; o > 0; o >>= 1) {
        lsum += __shfl_xor_sync(0xffffffffu, lsum, o);
        lsq  += __shfl_xor_sync(0xffffffffu, lsq,  o);
    }
    __shared__ float rs[4], rq[4];
    if (lane == 0) { rs[w] = lsum; rq[w] = lsq; }
    __syncthreads();
    float tot  = rs[0] + rs[1] + rs[2] + rs[3];
    float totq = rq[0] + rq[1] + rq[2] + rq[3];
    float mean = tot * (1.f / HIDD);
    float var  = totq * (1.f / HIDD) - mean * mean;
    float rstd = rsqrtf(var + 1e-5f);

#pragma unroll
    for (int k = 0; k < 6; k++) {
        int c = cb + 32 * k;
        float v = (acc[k] - mean) * rstd * gamma_l[c] + beta_l[c];
        v = fmaxf(v, 0.f);
        size_t idx = (size_t)i * HIDD + c;
        float nh = v + h[idx];
        h[idx] = nh;
        if (oh) {
            __nv_bfloat16 hh, ll;
            split_bf16(nh, hh, ll);
            oh[idx] = hh;
            ol[idx] = ll;
        }
    }
}

// ---------------- global mean pool (emits bf16 hi/lo directly) ----------------
__global__ void range_init()
{
    int b = blockIdx.x * blockDim.x + threadIdx.x;
    if (b < Bb) { g_start[b] = Nn; g_end[b] = 0; }
}

__global__ void range_kernel(const int* __restrict__ bv)
{
    int n = blockIdx.x * blockDim.x + threadIdx.x;
    if (n >= Nn) return;
    int b = bv[n];
    atomicMin(&g_start[b], n);
    atomicMax(&g_end[b], n + 1);
}

__global__ __launch_bounds__(256) void pool_kernel(
    __nv_bfloat16* __restrict__ oh, __nv_bfloat16* __restrict__ ol)
{
    int b = blockIdx.x;
    int s = g_start[b], e = g_end[b];
    float cnt = (e > s) ? (float)(e - s) : 1.0f;
    float invc = 1.f / cnt;
    for (int c = threadIdx.x; c < HIDD; c += 256) {
        float sum = 0.f;
        for (int n = s; n < e; n++) sum += g_h[(size_t)n * HIDD + c];
        float v = sum * invc;
        size_t idx = (size_t)b * HIDD + c;
        __nv_bfloat16 hh, ll;
        split_bf16(v, hh, ll);
        oh[idx] = hh;
        ol[idx] = ll;
    }
}

// ------------------------------------------------------------------------------
extern "C" void kernel_launch(void* const* d_in, const int* in_sizes, int n_in,
                              void* d_out, int out_size)
{
    const float* x       = (const float*)d_in[0];
    const int*   ei      = (const int*)  d_in[1];
    const int*   bv      = (const int*)  d_in[2];
    const float* W       = (const float*)d_in[3];
    const float* att_src = (const float*)d_in[4];
    const float* att_dst = (const float*)d_in[5];
    const float* bias    = (const float*)d_in[6];
    const float* gamma   = (const float*)d_in[7];
    const float* beta    = (const float*)d_in[8];
    const float* out_w   = (const float*)d_in[9];
    const float* out_b   = (const float*)d_in[10];
    float* out = (float*)d_out;

    float *h_p, *xw_p;
    int *deg_p, *cur_p;
    __nv_bfloat16 *ah_p, *al_p, *bh_p, *bl_p;
    cudaGetSymbolAddress((void**)&h_p,  g_h);
    cudaGetSymbolAddress((void**)&xw_p, g_xw);
    cudaGetSymbolAddress((void**)&deg_p, g_deg);
    cudaGetSymbolAddress((void**)&cur_p, g_cur);
    cudaGetSymbolAddress((void**)&ah_p, g_ah);
    cudaGetSymbolAddress((void**)&al_p, g_al);
    cudaGetSymbolAddress((void**)&bh_p, g_bh);
    cudaGetSymbolAddress((void**)&bl_p, g_bl);

    cudaFuncSetAttribute(gemm_mma, cudaFuncAttributeMaxDynamicSharedMemorySize, SMEMB);

    cudaMemsetAsync(deg_p, 0, Nn * sizeof(int));
    cudaMemsetAsync(cur_p, 0, Nn * sizeof(int));

    const int n4_h = Nn * HIDD / 4;
    init_cvt<<<(n4_h + 255) / 256, 256>>>((const float4*)x, (float4*)h_p,
                                          (__nv_bfloat162*)ah_p, (__nv_bfloat162*)al_p, n4_h);

    count_kernel  <<<(E2 + 255) / 256, 256>>>(ei);
    scan_kernel   <<<1, 1024>>>();
    scatter_kernel<<<(E2 + 255) / 256, 256>>>(ei);

    for (int l = 0; l < 2; l++) {
        wt_cvt<<<(HIDD * HIDD + 255) / 256, 256>>>(W + (size_t)l * HIDD * HIDD, bh_p, bl_p);
        gemm_mma<<<dim3(HIDD / 128, Nn / 128), 256, SMEMB>>>(ah_p, al_p, bh_p, bl_p,
                                                             xw_p, nullptr);
        alpha_kernel<<<(Nn * Hh) / 8, 256>>>(xw_p,
                                             att_src + l * Hh * Dd,
                                             att_dst + l * Hh * Dd);
        agg_ln_kernel<<<Nn, 128>>>(xw_p, bias + l * HIDD,
                                   gamma + l * HIDD, beta + l * HIDD, h_p,
                                   (l == 0) ? ah_p : (__nv_bfloat16*)nullptr,
                                   (l == 0) ? al_p : (__nv_bfloat16*)nullptr);
    }

    range_init <<<Bb / 256, 256>>>();
    range_kernel<<<Nn / 256, 256>>>(bv);
    pool_kernel <<<Bb, 256>>>(ah_p, al_p);

    wt_cvt<<<(HIDD * HIDD + 255) / 256, 256>>>(out_w, bh_p, bl_p);
    gemm_mma<<<dim3(HIDD / 128, Bb / 128), 256, SMEMB>>>(ah_p, al_p, bh_p, bl_p, out, out_b);
}